// round 16
// baseline (speedup 1.0000x reference)
#include <cuda_runtime.h>
#include <cstdint>

// CRF loss: inputs [1024,512,50] f32, transitions [50,50] f32,
// masks [1024,512] int32 (bool as i32), tag_indices [1024,512] i32.
// Output: [0] = loss scalar, [1..2500] = transitions passthrough.
// Strategy: persistent LPT queue, 64-thread blocks (warp0 fwd, warp1 bwd),
// EXP-SPACE recurrence: a_t = d_t (.) (E^T a_{t-1}), power-of-two renorm
// every 4 steps (exact), single lg2 at the end. No exp/log/shfl on the
// serial chain.

#define BSZ 1024
#define SLEN 512
#define NC 50
#define LOG2E 1.4426950408889634f
#define LN2   0.6931471805599453f
#define GRID_MAIN (148 * 6)

typedef unsigned long long ull;

__device__ float g_partial[BSZ];
__device__ int g_len[BSZ];
__device__ int g_order[BSZ];
__device__ unsigned int g_head = 0;
__device__ unsigned int g_count = 0;

__device__ __forceinline__ ull ffma2(ull a, ull b, ull c) {
    ull d;
    asm("fma.rn.f32x2 %0, %1, %2, %3;" : "=l"(d) : "l"(a), "l"(b), "l"(c));
    return d;
}
__device__ __forceinline__ ull fadd2(ull a, ull b) {
    ull d;
    asm("add.rn.f32x2 %0, %1, %2;" : "=l"(d) : "l"(a), "l"(b));
    return d;
}
__device__ __forceinline__ ull pack2(float lo, float hi) {
    ull d;
    asm("mov.b64 %0, {%1, %2};" : "=l"(d) : "f"(lo), "f"(hi));
    return d;
}
__device__ __forceinline__ void unpack2(float& lo, float& hi, ull v) {
    asm("mov.b64 {%0, %1}, %2;" : "=f"(lo), "=f"(hi) : "l"(v));
}
__device__ __forceinline__ float ex2f(float a) {
    float r; asm("ex2.approx.ftz.f32 %0, %1;" : "=f"(r) : "f"(a)); return r;
}
__device__ __forceinline__ float lg2f(float a) {
    float r; asm("lg2.approx.ftz.f32 %0, %1;" : "=f"(r) : "f"(a)); return r;
}

// s0,s1 = sum_{c1=0..49} p[c1] * {E0,E1}[c1]; p in buf as (p_2i, p_2i+1)
// float2 per lane-slot, E packed over c1 pairs (25 ull each).
__device__ __forceinline__ void matvec50(
    const float2* buf, const ull* E0, const ull* E1, float& s0, float& s1)
{
    const ulonglong2* pq = reinterpret_cast<const ulonglong2*>(buf);
    ull a0 = 0, a1 = 0, a2 = 0, a3 = 0;
    ull b0 = 0, b1 = 0, b2 = 0, b3 = 0;
    #pragma unroll
    for (int j = 0; j < 12; j += 2) {
        ulonglong2 v = pq[j];
        ulonglong2 w = pq[j + 1];
        a0 = ffma2(v.x, E0[2 * j],     a0);
        b0 = ffma2(v.x, E1[2 * j],     b0);
        a1 = ffma2(v.y, E0[2 * j + 1], a1);
        b1 = ffma2(v.y, E1[2 * j + 1], b1);
        a2 = ffma2(w.x, E0[2 * j + 2], a2);
        b2 = ffma2(w.x, E1[2 * j + 2], b2);
        a3 = ffma2(w.y, E0[2 * j + 3], a3);
        b3 = ffma2(w.y, E1[2 * j + 3], b3);
    }
    {
        ull last = reinterpret_cast<const ull*>(buf)[24];
        a0 = ffma2(last, E0[24], a0);
        b0 = ffma2(last, E1[24], b0);
    }
    a0 = fadd2(a0, a1); a2 = fadd2(a2, a3); a0 = fadd2(a0, a2);
    b0 = fadd2(b0, b1); b2 = fadd2(b2, b3); b0 = fadd2(b0, b2);
    float lo, hi;
    unpack2(lo, hi, a0); s0 = lo + hi;
    unpack2(lo, hi, b0); s1 = lo + hi;
}

// Forward step (exp space): a = d (.) (E^T a_prev). d precomputed.
__device__ __forceinline__ void fstep(
    float2 d, float2& a, float2* buf,
    const ull* E0, const ull* E1, bool act, int lane)
{
    if (act) buf[lane] = a;
    __syncwarp();
    float s0, s1;
    matvec50(buf, E0, E1, s0, s1);
    a.x = d.x * s0;
    a.y = d.y * s1;
}

// Backward step (exp space): B = E * (d (.) B_prev). d precomputed.
__device__ __forceinline__ void bstep(
    float2 d, float2& B, float2* buf,
    const ull* E0, const ull* E1, bool act, int lane)
{
    if (act) buf[lane] = make_float2(d.x * B.x, d.y * B.y);
    __syncwarp();
    float s0, s1;
    matvec50(buf, E0, E1, s0, s1);
    B.x = s0;
    B.y = s1;
}

// Power-of-two renorm: divide a by 2^e (e from shared ref value, uniform
// across lanes), accumulate e into esum. Exact in fp (no rounding).
__device__ __forceinline__ void renorm(
    float2& a, float& esum, const float2* lastbuf)
{
    float ref = lastbuf[0].x;          // state-0 value from last stored step
    int e = __float_as_int(ref) >> 23; // biased exponent (ref > 0, normal)
    e -= 127;
    float fac = __int_as_float((127 - e) << 23);   // 2^-e
    a.x *= fac;
    a.y *= fac;
    esum += (float)e;
}

// ---------- pre-pass 1: lengths + counter reset ----------
__global__ void __launch_bounds__(256) prep_len_kernel(
    const int* __restrict__ maskI)
{
    if (blockIdx.x == 0 && threadIdx.x == 0) { g_head = 0; g_count = 0; }
    int w = (blockIdx.x * blockDim.x + threadIdx.x) >> 5;   // row
    int lane = threadIdx.x & 31;
    if (w < BSZ) {
        const int4* m = reinterpret_cast<const int4*>(maskI + (size_t)w * SLEN);
        int s = 0;
        #pragma unroll
        for (int k = 0; k < 4; ++k) {
            int4 v = m[lane + 32 * k];
            s += v.x + v.y + v.z + v.w;
        }
        #pragma unroll
        for (int o = 16; o; o >>= 1)
            s += __shfl_xor_sync(0xffffffffu, s, o);
        if (lane == 0) g_len[w] = SLEN - s;   // monotone mask => [128,512]
    }
}

// ---------- pre-pass 2: counting sort by length, descending ----------
__global__ void __launch_bounds__(512) prep_sort_kernel()
{
    __shared__ int hist[SLEN + 1];
    __shared__ int start[SLEN + 1];
    int tid = threadIdx.x;
    for (int i = tid; i <= SLEN; i += 512) hist[i] = 0;
    __syncthreads();
    for (int b = tid; b < BSZ; b += 512) atomicAdd(&hist[g_len[b]], 1);
    __syncthreads();
    if (tid == 0) {
        int acc = 0;
        for (int L = SLEN; L >= 0; --L) { start[L] = acc; acc += hist[L]; }
    }
    __syncthreads();
    for (int b = tid; b < BSZ; b += 512) {
        int p = atomicAdd(&start[g_len[b]], 1);
        g_order[p] = b;
    }
}

// ---------- main: persistent blocks (6/SM), warp0 fwd / warp1 bwd ----------
__global__ void __launch_bounds__(64, 6) crf_main_kernel(
    const float* __restrict__ x,      // [BSZ, SLEN, NC]
    const float* __restrict__ T,      // [NC, NC]
    const int* __restrict__ tags,     // [BSZ, SLEN]
    float* __restrict__ out, int out_size)
{
    __shared__ float sT[NC * NC];
    __shared__ float2 sp[2][2][26];   // [warp][parity][lane-slot]
    __shared__ int stags[SLEN];
    __shared__ float shalf[2][52];    // log2-domain alpha_mid / beta_mid
    __shared__ float subs[2];
    __shared__ int srow;

    const int tid = threadIdx.x;
    const int wid = tid >> 5;         // 0 fwd, 1 bwd
    const int lane = tid & 31;
    const int c2 = 2 * lane;          // lane owns states c2, c2+1
    const bool act = (lane < 25);
    const bool isFwd = (wid == 0);

    for (int i = tid; i < NC * NC; i += 64) sT[i] = T[i];
    __syncthreads();

    // E = exp2(T * log2e). fwd: columns c2/c2+1 packed over c1 pairs;
    // bwd: rows c2/c2+1 packed over c' pairs. 50 ull = 100 regs.
    ull E0[25], E1[25];
    #pragma unroll
    for (int i = 0; i < 25; ++i) {
        float e00 = 0.f, e01 = 0.f, e10 = 0.f, e11 = 0.f;
        if (act) {
            if (isFwd) {
                e00 = ex2f(sT[(2 * i) * NC + c2] * LOG2E);
                e01 = ex2f(sT[(2 * i + 1) * NC + c2] * LOG2E);
                e10 = ex2f(sT[(2 * i) * NC + c2 + 1] * LOG2E);
                e11 = ex2f(sT[(2 * i + 1) * NC + c2 + 1] * LOG2E);
            } else {
                e00 = ex2f(sT[c2 * NC + 2 * i] * LOG2E);
                e01 = ex2f(sT[c2 * NC + 2 * i + 1] * LOG2E);
                e10 = ex2f(sT[(c2 + 1) * NC + 2 * i] * LOG2E);
                e11 = ex2f(sT[(c2 + 1) * NC + 2 * i + 1] * LOG2E);
            }
        }
        E0[i] = pack2(e00, e01);
        E1[i] = pack2(e10, e11);
    }

    float2* buf0 = sp[wid][0];
    float2* buf1 = sp[wid][1];

    while (true) {
        if (tid == 0) {
            unsigned int idx = atomicAdd(&g_head, 1u);
            srow = (idx < BSZ) ? g_order[idx] : -1;
        }
        __syncthreads();
        const int row = srow;
        if (row < 0) break;
        const int len = g_len[row];        // in [128, 512]
        const int mid = (len - 1) >> 1;
        const float* xrow = x + (size_t)row * SLEN * NC;

        const int* trow = tags + (size_t)row * SLEN;
        for (int i = tid; i < len; i += 64) stags[i] = trow[i];
        __syncthreads();

        // unary + binary split across both warps
        float ub = 0.f;
        for (int t = tid; t < len; t += 64) {
            int tg = stags[t];
            ub += __ldg(xrow + (size_t)t * NC + tg);
            if (t > 0) ub += sT[stags[t - 1] * NC + tg];
        }
        #pragma unroll
        for (int o = 16; o; o >>= 1)
            ub += __shfl_xor_sync(0xffffffffu, ub, o);
        if (lane == 0) subs[wid] = ub;

        // ---- recurrence in exp space ----
        // fwd: S = mid steps, step s consumes x[s] (as d).
        // bwd: S = len-1-mid steps, step s consumes x[len-s] (as d).
        const int S = isFwd ? mid : (len - 1 - mid);   // >= 63
        const float* xp;
        int str;
        float2 a;           // exp-space alpha (fwd) or beta (bwd)
        float esum = 0.f;
        if (isFwd) {
            xp = xrow + c2;
            str = NC;
            float2 x0 = act ? *reinterpret_cast<const float2*>(xrow + c2)
                            : make_float2(0.f, 0.f);
            a.x = ex2f(x0.x * LOG2E);   // a_0 = exp(x_0); inactive: garbage,
            a.y = ex2f(x0.y * LOG2E);   // never stored
        } else {
            xp = xrow + c2 + (size_t)len * NC;
            str = -NC;
            a = make_float2(1.f, 1.f);  // B_{len-1} = exp(0)
        }

        // prefetch x for steps 1..4, convert to d immediately (MUFU hidden)
        float2 d1, d2, d3, d4;
        {
            float2 t1 = make_float2(0.f, 0.f), t2 = t1, t3 = t1, t4 = t1;
            if (act) {
                t1 = *reinterpret_cast<const float2*>(xp + 1 * str);
                t2 = *reinterpret_cast<const float2*>(xp + 2 * str);
                t3 = *reinterpret_cast<const float2*>(xp + 3 * str);
                t4 = *reinterpret_cast<const float2*>(xp + 4 * str);
            }
            d1 = make_float2(ex2f(t1.x * LOG2E), ex2f(t1.y * LOG2E));
            d2 = make_float2(ex2f(t2.x * LOG2E), ex2f(t2.y * LOG2E));
            d3 = make_float2(ex2f(t3.x * LOG2E), ex2f(t3.y * LOG2E));
            d4 = make_float2(ex2f(t4.x * LOG2E), ex2f(t4.y * LOG2E));
        }

        int s = 1;
        for (; s + 7 <= S; s += 4) {
            float2 t1 = make_float2(0.f, 0.f), t2 = t1, t3 = t1, t4 = t1;
            if (act) {
                t1 = *reinterpret_cast<const float2*>(xp + (s + 4) * str);
                t2 = *reinterpret_cast<const float2*>(xp + (s + 5) * str);
                t3 = *reinterpret_cast<const float2*>(xp + (s + 6) * str);
                t4 = *reinterpret_cast<const float2*>(xp + (s + 7) * str);
            }
            if (isFwd) {
                fstep(d1, a, buf0, E0, E1, act, lane);
                fstep(d2, a, buf1, E0, E1, act, lane);
                fstep(d3, a, buf0, E0, E1, act, lane);
                fstep(d4, a, buf1, E0, E1, act, lane);
            } else {
                bstep(d1, a, buf0, E0, E1, act, lane);
                bstep(d2, a, buf1, E0, E1, act, lane);
                bstep(d3, a, buf0, E0, E1, act, lane);
                bstep(d4, a, buf1, E0, E1, act, lane);
            }
            renorm(a, esum, buf1);       // last store was in buf1
            d1 = make_float2(ex2f(t1.x * LOG2E), ex2f(t1.y * LOG2E));
            d2 = make_float2(ex2f(t2.x * LOG2E), ex2f(t2.y * LOG2E));
            d3 = make_float2(ex2f(t3.x * LOG2E), ex2f(t3.y * LOG2E));
            d4 = make_float2(ex2f(t4.x * LOG2E), ex2f(t4.y * LOG2E));
        }
        // epilogue: 4..7 steps remain; d1..d4 cover steps s..s+3
        if (isFwd) {
            fstep(d1, a, buf0, E0, E1, act, lane);
            fstep(d2, a, buf1, E0, E1, act, lane);
            fstep(d3, a, buf0, E0, E1, act, lane);
            fstep(d4, a, buf1, E0, E1, act, lane);
        } else {
            bstep(d1, a, buf0, E0, E1, act, lane);
            bstep(d2, a, buf1, E0, E1, act, lane);
            bstep(d3, a, buf0, E0, E1, act, lane);
            bstep(d4, a, buf1, E0, E1, act, lane);
        }
        renorm(a, esum, buf1);
        int parity = 0;
        for (int u = s + 4; u <= S; ++u) {
            float2 td = make_float2(0.f, 0.f);
            if (act)
                td = *reinterpret_cast<const float2*>(xp + u * str);
            float2 dd = make_float2(ex2f(td.x * LOG2E), ex2f(td.y * LOG2E));
            float2* bb = parity ? buf1 : buf0;
            if (isFwd) fstep(dd, a, bb, E0, E1, act, lane);
            else       bstep(dd, a, bb, E0, E1, act, lane);
            renorm(a, esum, bb);
            parity ^= 1;
        }

        // to log2 domain: value = lg2(a) + esum
        if (act) {
            shalf[wid][c2]     = lg2f(a.x) + esum;
            shalf[wid][c2 + 1] = lg2f(a.y) + esum;
        }
        __syncthreads();

        if (wid == 0) {
            // logZ = lse_c(alpha_mid[c] + beta_mid[c]), log2 domain
            float g0 = act ? shalf[0][c2] + shalf[1][c2] : -INFINITY;
            float g1 = act ? shalf[0][c2 + 1] + shalf[1][c2 + 1] : -INFINITY;
            float mx = fmaxf(g0, g1);
            #pragma unroll
            for (int o = 16; o; o >>= 1)
                mx = fmaxf(mx, __shfl_xor_sync(0xffffffffu, mx, o));
            float es = ex2f(g0 - mx) + ex2f(g1 - mx);
            #pragma unroll
            for (int o = 16; o; o >>= 1)
                es += __shfl_xor_sync(0xffffffffu, es, o);
            float log_norm = LN2 * (mx + lg2f(es));

            unsigned int ticket = 0;
            if (lane == 0) {
                g_partial[row] = subs[0] + subs[1] - log_norm;
                __threadfence();
                ticket = atomicAdd(&g_count, 1u);
            }
            ticket = __shfl_sync(0xffffffffu, ticket, 0);
            if (ticket == BSZ - 1) {
                __threadfence();
                float sm = 0.f;
                for (int i = lane; i < BSZ; i += 32) sm += g_partial[i];
                #pragma unroll
                for (int o = 16; o; o >>= 1)
                    sm += __shfl_xor_sync(0xffffffffu, sm, o);
                if (lane == 0) out[0] = -sm / (float)BSZ;
                if (out_size >= 1 + NC * NC) {
                    for (int i = lane; i < NC * NC; i += 32)
                        out[1 + i] = sT[i];
                }
            }
        }
        __syncthreads();   // protect shared state for next queue pop
    }
}

extern "C" void kernel_launch(void* const* d_in, const int* in_sizes, int n_in,
                              void* d_out, int out_size) {
    const float* x = (const float*)d_in[0];
    const float* T = (const float*)d_in[1];
    const int* maskI = (const int*)d_in[2];   // bool shipped as int32
    const int* tags = (const int*)d_in[3];
    float* out = (float*)d_out;
    (void)in_sizes; (void)n_in;

    prep_len_kernel<<<128, 256>>>(maskI);
    prep_sort_kernel<<<1, 512>>>();
    crf_main_kernel<<<GRID_MAIN, 64>>>(x, T, tags, out, out_size);
}